// round 16
// baseline (speedup 1.0000x reference)
#include <cuda_runtime.h>
#include <cuda_fp16.h>
#include <math.h>
#include <stdint.h>

#define NROWS 8192      // B*T
#define HD    640
#define NP    230
#define NM    96
#define TM    32        // rows per CTA
#define KC    32        // k per chunk
#define NCHUNK (HD / KC)  // 20
#define NKS16  (HD / 16)  // 40
#define P_PAD 258
#define M_PAD 97
#define MAXINV 32
#define NTHREADS 256

// ---- smem byte offsets ----
// A tile, fp16 FRAGMENT-PACKED: [blk 2][ks16 40][lane 32][reg 4] u32 = 40960 B
#define SM_PHONE 0                        // 32*258*4 = 33024 (aliases A region)
#define SM_PH    40960                    // 32*97*4 = 12416 -> 53376
#define SM_TBL   53376                    // icnt 96*4 -> 53760
#define SM_ILIST 53760                    // 96*32   -> 56832
#define SM_MAXV  56832                    // 32*4
#define SM_LSEV  56960                    // 32*4
#define SM_TOTAL 57088                    // x2 CTAs = 114176 < 228KB

// B packed as fp16x2, one uint4 per (nt, lane):
// [chunk][nt 32][lane 32][ks16 2][reg 2] uint32; 4096 uint32 per chunk.
__device__ uint32_t      g_Bp[NCHUNK * 4096];
__device__ int           g_icnt[NM];
__device__ unsigned char g_ilist[NM * MAXINV];

// ---------------- helpers ----------------
// m16n8k16 fp16 MMA, fp32 accum: D += A*B
__device__ __forceinline__ void mma_f16(float* d, uint32_t a0, uint32_t a1, uint32_t a2,
                                        uint32_t a3, uint32_t b0, uint32_t b1) {
    asm volatile(
        "mma.sync.aligned.m16n8k16.row.col.f32.f16.f16.f32 "
        "{%0,%1,%2,%3}, {%4,%5,%6,%7}, {%8,%9}, {%0,%1,%2,%3};"
        : "+f"(d[0]), "+f"(d[1]), "+f"(d[2]), "+f"(d[3])
        : "r"(a0), "r"(a1), "r"(a2), "r"(a3), "r"(b0), "r"(b1));
}
// pack two fp32 into fp16x2 (lo -> low half, hi -> high half)
__device__ __forceinline__ uint32_t packh2(float lo, float hi) {
    uint32_t r;
    asm("cvt.rn.f16x2.f32 %0, %1, %2;" : "=r"(r) : "f"(hi), "f"(lo));
    return r;
}

// ---------------- prologue kernel ----------------
// blocks 0..19: pack one 32-row chunk of B into fp16 fragment order (uint4 per nt,lane).
// blocks 20..31: inverse map, ONE phoneme per warp, rounds prefetched.
__global__ void prep_kernel(const float* __restrict__ f2p,
                            const float* __restrict__ mapping) {
    __shared__ float s[32 * 232];
    const int tid = threadIdx.x;
    const int b   = blockIdx.x;
    if (b < NCHUNK) {
        const float* src = f2p + (size_t)b * KC * NP;
        for (int idx = tid; idx < KC * NP; idx += 256) {
            int rr = idx / NP, c = idx - rr * NP;
            s[rr * 232 + c] = src[idx];
        }
        __syncthreads();
        uint32_t* dst = g_Bp + (size_t)b * 4096;
        for (int idx = tid; idx < 4096; idx += 256) {
            // idx = ((nt*32 + lane)*2 + ks)*2 + r2
            int r2   = idx & 1;
            int ks   = (idx >> 1) & 1;
            int lane = (idx >> 2) & 31;
            int nt   = idx >> 7;
            int n = nt * 8 + (lane >> 2);
            int k = ks * 16 + (lane & 3) * 2 + r2 * 8;     // within chunk
            float lo = (n < NP) ? s[k * 232 + n]       : 0.0f;
            float hi = (n < NP) ? s[(k + 1) * 232 + n] : 0.0f;
            dst[idx] = packh2(lo, hi);
        }
    } else {
        int wid  = tid >> 5;
        int lane = tid & 31;
        int m = (b - NCHUNK) * 8 + wid;   // 0..95
        bool hit[8];
        #pragma unroll
        for (int rr = 0; rr < 8; rr++) {
            int p = rr * 32 + lane;
            hit[rr] = (p < NP) && (mapping[m * NP + p] > 0.0f);
        }
        int cnt = 0;
        #pragma unroll
        for (int rr = 0; rr < 8; rr++) {
            unsigned bal = __ballot_sync(0xffffffffu, hit[rr]);
            if (hit[rr]) {
                int pos = cnt + __popc(bal & ((1u << lane) - 1u));
                if (pos < MAXINV) g_ilist[m * MAXINV + pos] = (unsigned char)(rr * 32 + lane);
            }
            cnt += __popc(bal);
        }
        if (lane == 0) g_icnt[m] = (cnt < MAXINV) ? cnt : MAXINV;
    }
}

// ---------------- main kernel ----------------
// 256 threads = 8 warps, each owns a 32-col slice (wn = wid); CTA tile 32 x 256.
// 2 CTAs per SM, 256 CTAs = one full wave on 148 SMs.
// A fragment-packed fp16 in smem (one LDS.128 per A-frag); B one LDG.128 per frag-pair.
__global__ __launch_bounds__(NTHREADS, 2)
void phon_mma_kernel(const float* __restrict__ enc, float* __restrict__ out) {
    extern __shared__ char smem[];
    const int tid  = threadIdx.x;
    const int wn   = tid >> 5;   // 0..7  (32-col slice)
    const int lane = tid & 31;
    const int row0 = blockIdx.x * TM;

    int*           sicnt  = (int*)(smem + SM_TBL);
    unsigned char* silist = (unsigned char*)(smem + SM_ILIST);
    float*         sMaxv  = (float*)(smem + SM_MAXV);
    float*         sLsev  = (float*)(smem + SM_LSEV);

    if (tid < NM) sicnt[tid] = g_icnt[tid];
    for (int i = tid; i < NM * MAXINV; i += NTHREADS) silist[i] = g_ilist[i];

    // stage A tile fp16 FRAGMENT-PACKED: 32 rows x 160 float4, 20 per thread.
    // dest word offset = ((blk*40 + ksi)*32 + lane)*4 + reg
    uint32_t* aw = (uint32_t*)smem;
    #pragma unroll
    for (int it = 0; it < 20; it++) {
        int idx = tid + it * NTHREADS;
        int r = idx / 160;           // 0..31
        int g = idx - r * 160;       // 0..159
        float4 v = *(const float4*)(enc + (size_t)(row0 + r) * HD + g * 4);
        int blk = r >> 4, rr = r & 15;
        int hi  = rr >> 3;
        int lrow = (rr & 7) * 4;
        int ksi = g >> 2;
        int p0  = (g & 3) * 2;       // pair index 0,2,4,6
        int base = (blk * NKS16 + ksi) * 32;
        // pair p: lane = lrow + (p&3), reg = (p>>2)*2 + hi
        aw[(base + lrow + (p0 & 3)) * 4 + ((p0 >> 2) * 2 + hi)]             = packh2(v.x, v.y);
        aw[(base + lrow + ((p0 + 1) & 3)) * 4 + (((p0 + 1) >> 2) * 2 + hi)] = packh2(v.z, v.w);
    }
    __syncthreads();

    const uint4* afp = (const uint4*)smem;   // fragment-packed A

    float acc[2][4][4];
    #pragma unroll
    for (int i = 0; i < 2; i++)
        #pragma unroll
        for (int j = 0; j < 4; j++)
            #pragma unroll
            for (int c = 0; c < 4; c++) acc[i][j][c] = 0.0f;

    uint4 bfrA[4], bfrB[4];   // [j]: .x=ks0b0 .y=ks0b1 .z=ks1b0 .w=ks1b1

    auto load_b = [&](int kc, uint4* bfr) {
        const uint32_t* bch = g_Bp + (size_t)kc * 4096;
        #pragma unroll
        for (int j = 0; j < 4; j++) {
            int nt = wn * 4 + j;
            bfr[j] = __ldg((const uint4*)(bch + ((nt * 32 + lane) << 2)));
        }
    };

    auto mma_chunk = [&](const uint4* bfr, int kc) {
        #pragma unroll
        for (int ks = 0; ks < 2; ks++) {
            const int kci = kc * 2 + ks;
            uint4 a0 = afp[(0 * NKS16 + kci) * 32 + lane];   // rows 0-15
            uint4 a1 = afp[(1 * NKS16 + kci) * 32 + lane];   // rows 16-31
            #pragma unroll
            for (int j = 0; j < 4; j++) {
                uint32_t b0 = ks ? bfr[j].z : bfr[j].x;
                uint32_t b1 = ks ? bfr[j].w : bfr[j].y;
                mma_f16(acc[0][j], a0.x, a0.y, a0.z, a0.w, b0, b1);
                mma_f16(acc[1][j], a1.x, a1.y, a1.z, a1.w, b0, b1);
            }
        }
    };

    // barrier-free mainloop, unrolled x2 to ping-pong B register buffers
    load_b(0, bfrA);
    #pragma unroll 1
    for (int kc = 0; kc < NCHUNK; kc += 2) {
        if (kc + 1 < NCHUNK) load_b(kc + 1, bfrB);
        mma_chunk(bfrA, kc);
        if (kc + 2 < NCHUNK) load_b(kc + 2, bfrA);
        mma_chunk(bfrB, kc + 1);
    }
    __syncthreads();   // all warps done reading A frags before epilogue aliases them

    // ---- epilogue ----
    const float scale = 0.039528470752104741f;  // 1/sqrt(640)
    float* sPhone = (float*)(smem + SM_PHONE);
    float* sPh    = (float*)(smem + SM_PH);

    #pragma unroll
    for (int i = 0; i < 2; i++) {
        int r = i * 16 + (lane >> 2);
        #pragma unroll
        for (int j = 0; j < 4; j++) {
            int c = wn * 32 + j * 8 + (lane & 3) * 2;
            float2 v0 = make_float2(acc[i][j][0] * scale, acc[i][j][1] * scale);
            float2 v1 = make_float2(acc[i][j][2] * scale, acc[i][j][3] * scale);
            *(float2*)(sPhone + r * P_PAD + c)       = v0;
            *(float2*)(sPhone + (r + 8) * P_PAD + c) = v1;
        }
    }
    __syncthreads();

    // gather-max via inverse map: 32 rows x 96 phonemes
    for (int idx = tid; idx < TM * NM; idx += NTHREADS) {
        int r = idx / NM;
        int m = idx - r * NM;
        int cnt = sicnt[m];
        const unsigned char* lst = silist + m * MAXINV;
        float mx = -INFINITY;
        for (int c = 0; c < cnt; c++)
            mx = fmaxf(mx, sPhone[r * P_PAD + lst[c]]);
        sPh[r * M_PAD + m] = mx;
    }
    __syncthreads();

    // per-row max + logsumexp: 4 threads per row (first 128 threads)
    if (tid < TM * 4) {
        int r = tid >> 2;
        int q = tid & 3;
        const float* row = sPh + r * M_PAD;
        float mx = -INFINITY;
        #pragma unroll
        for (int m = q * 24; m < q * 24 + 24; m++) mx = fmaxf(mx, row[m]);
        mx = fmaxf(mx, __shfl_xor_sync(0xffffffffu, mx, 1));
        mx = fmaxf(mx, __shfl_xor_sync(0xffffffffu, mx, 2));
        float s = 0.0f;
        #pragma unroll
        for (int m = q * 24; m < q * 24 + 24; m++) s += expf(row[m] - mx);
        s += __shfl_xor_sync(0xffffffffu, s, 1);
        s += __shfl_xor_sync(0xffffffffu, s, 2);
        if (q == 0) { sMaxv[r] = mx; sLsev[r] = logf(s); }
    }
    __syncthreads();

    // coalesced output
    for (int idx = tid; idx < TM * NM; idx += NTHREADS) {
        int r = idx / NM;
        int m = idx - r * NM;
        out[(size_t)(row0 + r) * NM + m] = sPh[r * M_PAD + m] - sMaxv[r] - sLsev[r];
    }
}

extern "C" void kernel_launch(void* const* d_in, const int* in_sizes, int n_in,
                              void* d_out, int out_size) {
    const float* enc     = (const float*)d_in[0];
    const float* f2p     = (const float*)d_in[1];
    const float* mapping = (const float*)d_in[2];
    float*       out     = (float*)d_out;

    cudaFuncSetAttribute(phon_mma_kernel,
                         cudaFuncAttributeMaxDynamicSharedMemorySize, SM_TOTAL);

    prep_kernel<<<NCHUNK + 12, 256>>>(f2p, mapping);
    phon_mma_kernel<<<NROWS / TM, NTHREADS, SM_TOTAL>>>(enc, out);
}

// round 17
// speedup vs baseline: 1.0667x; 1.0667x over previous
#include <cuda_runtime.h>
#include <cuda_fp16.h>
#include <math.h>
#include <stdint.h>

#define NROWS 8192      // B*T
#define HD    640
#define NP    230
#define NM    96
#define TM    64        // rows per CTA
#define KC    32        // k per chunk
#define NCHUNK (HD / KC)  // 20
#define NKS16  (HD / 16)  // 40
#define P_PAD 258
#define M_PAD 97
#define MAXINV 32
#define NTHREADS 512

// ---- smem byte offsets ----
// A tile, fp16 FRAGMENT-PACKED: [blk 4][ks16 40][lane 32][reg 4] u32 = 81920 B
#define SM_PHONE 0                        // 64*258*4 = 66048 (< 81920, aliases A region)
#define SM_PH    81920                    // 64*97*4 = 24832 -> 106752
#define SM_TBL   106752                   // icnt 96*4 -> 107136
#define SM_ILIST 107136                   // 96*32   -> 110208
#define SM_MAXV  110208                   // 64*4
#define SM_LSEV  110464                   // 64*4
#define SM_TOTAL 110720

// B packed as fp16x2, one uint4 per (nt, lane):
// [chunk][nt 32][lane 32][ks16 2][reg 2] uint32; 4096 uint32 per chunk.
__device__ uint32_t      g_Bp[NCHUNK * 4096];
__device__ int           g_icnt[NM];
__device__ unsigned char g_ilist[NM * MAXINV];

// ---------------- helpers ----------------
// m16n8k16 fp16 MMA, fp32 accum: D += A*B
__device__ __forceinline__ void mma_f16(float* d, uint32_t a0, uint32_t a1, uint32_t a2,
                                        uint32_t a3, uint32_t b0, uint32_t b1) {
    asm volatile(
        "mma.sync.aligned.m16n8k16.row.col.f32.f16.f16.f32 "
        "{%0,%1,%2,%3}, {%4,%5,%6,%7}, {%8,%9}, {%0,%1,%2,%3};"
        : "+f"(d[0]), "+f"(d[1]), "+f"(d[2]), "+f"(d[3])
        : "r"(a0), "r"(a1), "r"(a2), "r"(a3), "r"(b0), "r"(b1));
}
// pack two fp32 into fp16x2 (lo -> low half, hi -> high half)
__device__ __forceinline__ uint32_t packh2(float lo, float hi) {
    uint32_t r;
    asm("cvt.rn.f16x2.f32 %0, %1, %2;" : "=r"(r) : "f"(hi), "f"(lo));
    return r;
}

// ---------------- prologue kernel ----------------
// blocks 0..19: pack one 32-row chunk of B into fp16 fragment order (uint4 per nt,lane).
// blocks 20..31: inverse map, ONE phoneme per warp, rounds prefetched.
__global__ void prep_kernel(const float* __restrict__ f2p,
                            const float* __restrict__ mapping) {
    __shared__ float s[32 * 232];
    const int tid = threadIdx.x;
    const int b   = blockIdx.x;
    if (b < NCHUNK) {
        const float* src = f2p + (size_t)b * KC * NP;
        for (int idx = tid; idx < KC * NP; idx += 256) {
            int rr = idx / NP, c = idx - rr * NP;
            s[rr * 232 + c] = src[idx];
        }
        __syncthreads();
        uint32_t* dst = g_Bp + (size_t)b * 4096;
        for (int idx = tid; idx < 4096; idx += 256) {
            // idx = ((nt*32 + lane)*2 + ks)*2 + r2
            int r2   = idx & 1;
            int ks   = (idx >> 1) & 1;
            int lane = (idx >> 2) & 31;
            int nt   = idx >> 7;
            int n = nt * 8 + (lane >> 2);
            int k = ks * 16 + (lane & 3) * 2 + r2 * 8;     // within chunk
            float lo = (n < NP) ? s[k * 232 + n]       : 0.0f;
            float hi = (n < NP) ? s[(k + 1) * 232 + n] : 0.0f;
            dst[idx] = packh2(lo, hi);
        }
    } else {
        int wid  = tid >> 5;
        int lane = tid & 31;
        int m = (b - NCHUNK) * 8 + wid;   // 0..95
        bool hit[8];
        #pragma unroll
        for (int rr = 0; rr < 8; rr++) {
            int p = rr * 32 + lane;
            hit[rr] = (p < NP) && (mapping[m * NP + p] > 0.0f);
        }
        int cnt = 0;
        #pragma unroll
        for (int rr = 0; rr < 8; rr++) {
            unsigned bal = __ballot_sync(0xffffffffu, hit[rr]);
            if (hit[rr]) {
                int pos = cnt + __popc(bal & ((1u << lane) - 1u));
                if (pos < MAXINV) g_ilist[m * MAXINV + pos] = (unsigned char)(rr * 32 + lane);
            }
            cnt += __popc(bal);
        }
        if (lane == 0) g_icnt[m] = (cnt < MAXINV) ? cnt : MAXINV;
    }
}

// ---------------- main kernel ----------------
// 512 threads = 16 warps (2 x 8); warp tile 32 x 32, fp16 m16n8k16.
// A fragment-packed fp16 in smem (one LDS.128 per A-frag); B one LDG.128 per frag-pair.
// Barrier-free mainloop; 128 CTAs, 1 per SM.
__global__ __launch_bounds__(NTHREADS, 1)
void phon_mma_kernel(const float* __restrict__ enc, float* __restrict__ out) {
    extern __shared__ char smem[];
    const int tid  = threadIdx.x;
    const int wid  = tid >> 5;
    const int lane = tid & 31;
    const int wm   = wid >> 3;   // 0..1  (32-row slice)
    const int wn   = wid & 7;    // 0..7  (32-col slice)
    const int row0 = blockIdx.x * TM;

    int*           sicnt  = (int*)(smem + SM_TBL);
    unsigned char* silist = (unsigned char*)(smem + SM_ILIST);
    float*         sMaxv  = (float*)(smem + SM_MAXV);
    float*         sLsev  = (float*)(smem + SM_LSEV);

    if (tid < NM) sicnt[tid] = g_icnt[tid];
    for (int i = tid; i < NM * MAXINV; i += NTHREADS) silist[i] = g_ilist[i];

    // stage A tile fp16 FRAGMENT-PACKED: 64 rows x 160 float4, 20 per thread.
    // dest word offset = ((blk*40 + ksi)*32 + lane)*4 + reg,  blk = row/16
    uint32_t* aw = (uint32_t*)smem;
    #pragma unroll
    for (int it = 0; it < 20; it++) {
        int idx = tid + it * NTHREADS;
        int r = idx / 160;           // 0..63
        int g = idx - r * 160;       // 0..159
        float4 v = *(const float4*)(enc + (size_t)(row0 + r) * HD + g * 4);
        int blk = r >> 4, rr = r & 15;
        int hi  = rr >> 3;
        int lrow = (rr & 7) * 4;
        int ksi = g >> 2;
        int p0  = (g & 3) * 2;       // pair index 0,2,4,6
        int base = (blk * NKS16 + ksi) * 32;
        // pair p: lane = lrow + (p&3), reg = (p>>2)*2 + hi
        aw[(base + lrow + (p0 & 3)) * 4 + ((p0 >> 2) * 2 + hi)]             = packh2(v.x, v.y);
        aw[(base + lrow + ((p0 + 1) & 3)) * 4 + (((p0 + 1) >> 2) * 2 + hi)] = packh2(v.z, v.w);
    }
    __syncthreads();

    const uint4* afp = (const uint4*)smem;   // fragment-packed A

    float acc[2][4][4];
    #pragma unroll
    for (int i = 0; i < 2; i++)
        #pragma unroll
        for (int j = 0; j < 4; j++)
            #pragma unroll
            for (int c = 0; c < 4; c++) acc[i][j][c] = 0.0f;

    uint4 bfrA[4], bfrB[4];   // [j]: .x=ks0b0 .y=ks0b1 .z=ks1b0 .w=ks1b1

    auto load_b = [&](int kc, uint4* bfr) {
        const uint32_t* bch = g_Bp + (size_t)kc * 4096;
        #pragma unroll
        for (int j = 0; j < 4; j++) {
            int nt = wn * 4 + j;
            bfr[j] = __ldg((const uint4*)(bch + ((nt * 32 + lane) << 2)));
        }
    };

    auto mma_chunk = [&](const uint4* bfr, int kc) {
        #pragma unroll
        for (int ks = 0; ks < 2; ks++) {
            const int kci = kc * 2 + ks;
            uint4 a0 = afp[((wm * 2 + 0) * NKS16 + kci) * 32 + lane];   // rows wm*32+0..15
            uint4 a1 = afp[((wm * 2 + 1) * NKS16 + kci) * 32 + lane];   // rows wm*32+16..31
            #pragma unroll
            for (int j = 0; j < 4; j++) {
                uint32_t b0 = ks ? bfr[j].z : bfr[j].x;
                uint32_t b1 = ks ? bfr[j].w : bfr[j].y;
                mma_f16(acc[0][j], a0.x, a0.y, a0.z, a0.w, b0, b1);
                mma_f16(acc[1][j], a1.x, a1.y, a1.z, a1.w, b0, b1);
            }
        }
    };

    // barrier-free mainloop, unrolled x2 to ping-pong B register buffers
    load_b(0, bfrA);
    #pragma unroll 1
    for (int kc = 0; kc < NCHUNK; kc += 2) {
        if (kc + 1 < NCHUNK) load_b(kc + 1, bfrB);
        mma_chunk(bfrA, kc);
        if (kc + 2 < NCHUNK) load_b(kc + 2, bfrA);
        mma_chunk(bfrB, kc + 1);
    }
    __syncthreads();   // all warps done reading A frags before epilogue aliases them

    // ---- epilogue ----
    const float scale = 0.039528470752104741f;  // 1/sqrt(640)
    float* sPhone = (float*)(smem + SM_PHONE);
    float* sPh    = (float*)(smem + SM_PH);

    #pragma unroll
    for (int i = 0; i < 2; i++) {
        int r = wm * 32 + i * 16 + (lane >> 2);
        #pragma unroll
        for (int j = 0; j < 4; j++) {
            int c = wn * 32 + j * 8 + (lane & 3) * 2;
            float2 v0 = make_float2(acc[i][j][0] * scale, acc[i][j][1] * scale);
            float2 v1 = make_float2(acc[i][j][2] * scale, acc[i][j][3] * scale);
            *(float2*)(sPhone + r * P_PAD + c)       = v0;
            *(float2*)(sPhone + (r + 8) * P_PAD + c) = v1;
        }
    }
    __syncthreads();

    // gather-max via inverse map: 64 rows x 96 phonemes
    for (int idx = tid; idx < TM * NM; idx += NTHREADS) {
        int r = idx / NM;
        int m = idx - r * NM;
        int cnt = sicnt[m];
        const unsigned char* lst = silist + m * MAXINV;
        float mx = -INFINITY;
        for (int c = 0; c < cnt; c++)
            mx = fmaxf(mx, sPhone[r * P_PAD + lst[c]]);
        sPh[r * M_PAD + m] = mx;
    }
    __syncthreads();

    // per-row max + logsumexp: 4 threads per row (first 256 threads)
    if (tid < 256) {
        int r = tid >> 2;
        int q = tid & 3;
        const float* row = sPh + r * M_PAD;
        float mx = -INFINITY;
        #pragma unroll
        for (int m = q * 24; m < q * 24 + 24; m++) mx = fmaxf(mx, row[m]);
        mx = fmaxf(mx, __shfl_xor_sync(0xffffffffu, mx, 1));
        mx = fmaxf(mx, __shfl_xor_sync(0xffffffffu, mx, 2));
        float s = 0.0f;
        #pragma unroll
        for (int m = q * 24; m < q * 24 + 24; m++) s += expf(row[m] - mx);
        s += __shfl_xor_sync(0xffffffffu, s, 1);
        s += __shfl_xor_sync(0xffffffffu, s, 2);
        if (q == 0) { sMaxv[r] = mx; sLsev[r] = logf(s); }
    }
    __syncthreads();

    // coalesced output
    for (int idx = tid; idx < TM * NM; idx += NTHREADS) {
        int r = idx / NM;
        int m = idx - r * NM;
        out[(size_t)(row0 + r) * NM + m] = sPh[r * M_PAD + m] - sMaxv[r] - sLsev[r];
    }
}

extern "C" void kernel_launch(void* const* d_in, const int* in_sizes, int n_in,
                              void* d_out, int out_size) {
    const float* enc     = (const float*)d_in[0];
    const float* f2p     = (const float*)d_in[1];
    const float* mapping = (const float*)d_in[2];
    float*       out     = (float*)d_out;

    cudaFuncSetAttribute(phon_mma_kernel,
                         cudaFuncAttributeMaxDynamicSharedMemorySize, SM_TOTAL);

    prep_kernel<<<NCHUNK + 12, 256>>>(f2p, mapping);
    phon_mma_kernel<<<NROWS / TM, NTHREADS, SM_TOTAL>>>(enc, out);
}